// round 1
// baseline (speedup 1.0000x reference)
#include <cuda_runtime.h>
#include <math.h>

// ---------------------------------------------------------------------------
// Scratch (static device globals — no allocations)
// ---------------------------------------------------------------------------
#define NBINS 4096
__device__ unsigned int g_hist[4][NBINS];   // slot = level*2 + tensor
__device__ unsigned int g_maxbits[2];
__device__ float        g_tau[2];
__device__ float        g_lo[2];
__device__ float        g_w[2];
__device__ unsigned int g_rank[2];

// ---------------------------------------------------------------------------
// Zero / init scratch (runs every replay inside the graph)
// ---------------------------------------------------------------------------
__global__ void zero_kernel(unsigned int rank)
{
    int i = blockIdx.x * blockDim.x + threadIdx.x;
    int total = 4 * NBINS;
    for (; i < total; i += gridDim.x * blockDim.x)
        ((unsigned int*)g_hist)[i] = 0u;
    if (blockIdx.x == 0 && threadIdx.x < 2) {
        int t = threadIdx.x;
        g_maxbits[t] = 0u;
        g_lo[t]      = 0.0f;
        g_w[t]       = 16.0f / (float)NBINS;   // 1/256 (exact)
        g_rank[t]    = rank;
        g_tau[t]     = 0.0f;
    }
}

// ---------------------------------------------------------------------------
// Histogram pass (shared-memory privatized, float4 loads)
// slot = level*2 + t ; range [g_lo, g_lo + NBINS*g_w)
// ---------------------------------------------------------------------------
__global__ void hist_kernel(const float* __restrict__ x, int n4, int slot)
{
    __shared__ unsigned int sh[NBINS];
    for (int i = threadIdx.x; i < NBINS; i += blockDim.x) sh[i] = 0u;
    __syncthreads();

    int t = slot & 1;
    float lo   = g_lo[t];
    float invw = 1.0f / g_w[t];      // power of two -> exact

    int stride = gridDim.x * blockDim.x;
    for (int i = blockIdx.x * blockDim.x + threadIdx.x; i < n4; i += stride) {
        float4 v = ((const float4*)x)[i];
        float a, r;
        a = fabsf(v.x); r = (a - lo) * invw;
        if (r >= 0.0f && r < (float)NBINS) atomicAdd(&sh[(int)r], 1u);
        a = fabsf(v.y); r = (a - lo) * invw;
        if (r >= 0.0f && r < (float)NBINS) atomicAdd(&sh[(int)r], 1u);
        a = fabsf(v.z); r = (a - lo) * invw;
        if (r >= 0.0f && r < (float)NBINS) atomicAdd(&sh[(int)r], 1u);
        a = fabsf(v.w); r = (a - lo) * invw;
        if (r >= 0.0f && r < (float)NBINS) atomicAdd(&sh[(int)r], 1u);
    }
    __syncthreads();
    for (int i = threadIdx.x; i < NBINS; i += blockDim.x) {
        unsigned int c = sh[i];
        if (c) atomicAdd(&g_hist[slot][i], c);
    }
}

// ---------------------------------------------------------------------------
// Pick the bin containing rank g_rank[t]; either narrow the range (level 0)
// or finalize tau (level 1). One block, 256 threads, 16 bins/thread.
// ---------------------------------------------------------------------------
__global__ void pick_kernel(int t, int slot, int finalize)
{
    __shared__ unsigned int csum[256];
    __shared__ unsigned int pre[256];
    int tid = threadIdx.x;

    unsigned int local[16];
    unsigned int s = 0;
#pragma unroll
    for (int i = 0; i < 16; i++) {
        local[i] = g_hist[slot][tid * 16 + i];
        s += local[i];
    }
    csum[tid] = s;
    __syncthreads();
    if (tid == 0) {
        unsigned int acc = 0;
        for (int i = 0; i < 256; i++) { pre[i] = acc; acc += csum[i]; }
    }
    __syncthreads();

    unsigned int r = g_rank[t];
    if (pre[tid] <= r && r < pre[tid] + csum[tid]) {
        unsigned int acc = pre[tid];
#pragma unroll
        for (int i = 0; i < 16; i++) {
            if (r < acc + local[i]) {
                int b    = tid * 16 + i;
                float w  = g_w[t];
                float lo = g_lo[t] + (float)b * w;
                if (finalize) {
                    g_tau[t] = lo + 0.5f * w;
                } else {
                    g_lo[t]   = lo;
                    g_w[t]    = w / (float)NBINS;   // -> 2^-20 (exact)
                    g_rank[t] = r - acc;
                }
                break;
            }
            acc += local[i];
        }
    }
}

// ---------------------------------------------------------------------------
// Max of |x| over elements with |x| < tau  (full tensor)
// ---------------------------------------------------------------------------
__global__ void max_kernel(const float* __restrict__ x, int n4, int t)
{
    float tau = g_tau[t];
    float m = 0.0f;
    int stride = gridDim.x * blockDim.x;
    for (int i = blockIdx.x * blockDim.x + threadIdx.x; i < n4; i += stride) {
        float4 v = ((const float4*)x)[i];
        float a;
        a = fabsf(v.x); if (a < tau) m = fmaxf(m, a);
        a = fabsf(v.y); if (a < tau) m = fmaxf(m, a);
        a = fabsf(v.z); if (a < tau) m = fmaxf(m, a);
        a = fabsf(v.w); if (a < tau) m = fmaxf(m, a);
    }
#pragma unroll
    for (int o = 16; o > 0; o >>= 1)
        m = fmaxf(m, __shfl_xor_sync(0xffffffffu, m, o));
    if ((threadIdx.x & 31) == 0)
        atomicMax(&g_maxbits[t], __float_as_uint(m));   // nonneg floats: bit order == value order
}

// ---------------------------------------------------------------------------
// Quantize round-trip:  out = outlier ? x : clip(rint(x/scale),-128,127)*scale
// ---------------------------------------------------------------------------
__global__ void quant_kernel(const float* __restrict__ x, int n4, int t,
                             float* __restrict__ out)
{
    float tau   = g_tau[t];
    float scale = __fdiv_rn(__uint_as_float(g_maxbits[t]), 127.0f);
    int stride = gridDim.x * blockDim.x;
    for (int i = blockIdx.x * blockDim.x + threadIdx.x; i < n4; i += stride) {
        float4 v = ((const float4*)x)[i];
        float4 o;
        float a;
        a = fabsf(v.x);
        o.x = (a >= tau) ? v.x
              : fminf(fmaxf(rintf(__fdiv_rn(v.x, scale)), -128.0f), 127.0f) * scale;
        a = fabsf(v.y);
        o.y = (a >= tau) ? v.y
              : fminf(fmaxf(rintf(__fdiv_rn(v.y, scale)), -128.0f), 127.0f) * scale;
        a = fabsf(v.z);
        o.z = (a >= tau) ? v.z
              : fminf(fmaxf(rintf(__fdiv_rn(v.z, scale)), -128.0f), 127.0f) * scale;
        a = fabsf(v.w);
        o.w = (a >= tau) ? v.w
              : fminf(fmaxf(rintf(__fdiv_rn(v.w, scale)), -128.0f), 127.0f) * scale;
        ((float4*)out)[i] = o;
    }
}

// ---------------------------------------------------------------------------
// Batched SGEMM: C[b] = A[b] (2048x2048, row-major) * B[b] (2048x2048, row-major)
// 128x128 block tile, BK=16, 256 threads, 8x8 per-thread micro-tile.
// ---------------------------------------------------------------------------
#define GM 2048
#define GK 2048
#define GN 2048
#define BM 128
#define BN 128
#define BK 16
#define TM 8
#define TN 8

__global__ void __launch_bounds__(256, 2)
gemm_kernel(const float* __restrict__ A, const float* __restrict__ B,
            float* __restrict__ C)
{
    const size_t bofs = (size_t)blockIdx.z * (size_t)GM * (size_t)GK;
    const float* Ab = A + bofs;
    const float* Bb = B + bofs;
    float*       Cb = C + (size_t)blockIdx.z * (size_t)GM * (size_t)GN;

    const int brow = blockIdx.y * BM;
    const int bcol = blockIdx.x * BN;

    __shared__ float As[BK][BM];
    __shared__ float Bs[BK][BN];

    const int tid = threadIdx.x;
    const int tx  = tid & 15;   // 0..15 -> column group
    const int ty  = tid >> 4;   // 0..15 -> row group

    float acc[TM][TN];
#pragma unroll
    for (int i = 0; i < TM; i++)
#pragma unroll
        for (int j = 0; j < TN; j++) acc[i][j] = 0.0f;

    for (int k0 = 0; k0 < GK; k0 += BK) {
        // Load A tile (128 rows x 16 k) and B tile (16 k x 128 cols), float4
#pragma unroll
        for (int s = tid; s < 512; s += 256) {
            // A: slot -> (row, k-group)
            int ar  = s >> 2;
            int ac4 = s & 3;
            float4 av = *(const float4*)&Ab[(size_t)(brow + ar) * GK + k0 + ac4 * 4];
            As[ac4 * 4 + 0][ar] = av.x;
            As[ac4 * 4 + 1][ar] = av.y;
            As[ac4 * 4 + 2][ar] = av.z;
            As[ac4 * 4 + 3][ar] = av.w;
            // B: slot -> (k, col-group)
            int bk  = s >> 5;
            int bn4 = s & 31;
            float4 bv = *(const float4*)&Bb[(size_t)(k0 + bk) * GN + bcol + bn4 * 4];
            *(float4*)&Bs[bk][bn4 * 4] = bv;
        }
        __syncthreads();

#pragma unroll
        for (int kk = 0; kk < BK; kk++) {
            float a[TM], b[TN];
#pragma unroll
            for (int i = 0; i < TM; i++) a[i] = As[kk][ty * TM + i];
#pragma unroll
            for (int j = 0; j < TN; j++) b[j] = Bs[kk][tx * TN + j];
#pragma unroll
            for (int i = 0; i < TM; i++)
#pragma unroll
                for (int j = 0; j < TN; j++)
                    acc[i][j] += a[i] * b[j];
        }
        __syncthreads();
    }

#pragma unroll
    for (int i = 0; i < TM; i++) {
        int row = brow + ty * TM + i;
#pragma unroll
        for (int j4 = 0; j4 < TN; j4 += 4) {
            float4 v = make_float4(acc[i][j4], acc[i][j4 + 1],
                                   acc[i][j4 + 2], acc[i][j4 + 3]);
            *(float4*)&Cb[(size_t)row * GN + bcol + tx * TN + j4] = v;
        }
    }
}

// ---------------------------------------------------------------------------
// Launch
// ---------------------------------------------------------------------------
extern "C" void kernel_launch(void* const* d_in, const int* in_sizes, int n_in,
                              void* d_out, int out_size)
{
    const float* x1 = (const float*)d_in[0];   // [2,8,2048,2048]
    const float* x2 = (const float*)d_in[1];   // [2,8,2048,2048] (D,S layout)
    float* out = (float*)d_out;

    const long long n  = (long long)in_sizes[0];   // 67108864
    const long long n0 = n / 2;                    // first batch element
    const int n4  = (int)(n  / 4);
    const int n04 = (int)(n0 / 4);

    // jnp.quantile 'linear': h = q*(N-1), lower index = floor(h)
    double h = 0.99 * (double)(n0 - 1);
    unsigned int rank = (unsigned int)h;

    float* res = out;
    float* x1h = out + n;
    float* x2h = out + 2 * n;

    zero_kernel<<<64, 256>>>(rank);

    // Main GEMM (16 batched 2048^3)
    dim3 grid(GN / BN, GM / BM, 16);
    gemm_kernel<<<grid, 256>>>(x1, x2, res);

    // tau for x1 (two-level histogram over |x1[0]|)
    hist_kernel<<<1184, 256>>>(x1, n04, 0);
    pick_kernel<<<1, 256>>>(0, 0, 0);
    hist_kernel<<<1184, 256>>>(x1, n04, 2);
    pick_kernel<<<1, 256>>>(0, 2, 1);

    // tau for x2 (transpose-invariant: same element set)
    hist_kernel<<<1184, 256>>>(x2, n04, 1);
    pick_kernel<<<1, 256>>>(1, 1, 0);
    hist_kernel<<<1184, 256>>>(x2, n04, 3);
    pick_kernel<<<1, 256>>>(1, 3, 1);

    // scale = max(|resid|)/127 over full tensors
    max_kernel<<<2048, 256>>>(x1, n4, 0);
    max_kernel<<<2048, 256>>>(x2, n4, 1);

    // quantize round-trips
    quant_kernel<<<2048, 256>>>(x1, n4, 0, x1h);
    quant_kernel<<<2048, 256>>>(x2, n4, 1, x2h);
}

// round 4
// speedup vs baseline: 2.5817x; 2.5817x over previous
#include <cuda_runtime.h>
#include <math.h>
#include <cstdint>

// ===========================================================================
// Scratch for compression pipeline (static device globals)
// ===========================================================================
#define NBINS 4096
__device__ unsigned int g_hist[4][NBINS];
__device__ unsigned int g_maxbits[2];
__device__ float        g_tau[2];
__device__ float        g_lo[2];
__device__ float        g_w[2];
__device__ unsigned int g_rank[2];

__global__ void zero_kernel(unsigned int rank)
{
    int i = blockIdx.x * blockDim.x + threadIdx.x;
    int total = 4 * NBINS;
    for (; i < total; i += gridDim.x * blockDim.x)
        ((unsigned int*)g_hist)[i] = 0u;
    if (blockIdx.x == 0 && threadIdx.x < 2) {
        int t = threadIdx.x;
        g_maxbits[t] = 0u;
        g_lo[t]      = 0.0f;
        g_w[t]       = 16.0f / (float)NBINS;
        g_rank[t]    = rank;
        g_tau[t]     = 0.0f;
    }
}

__global__ void hist_kernel(const float* __restrict__ x, int n4, int slot)
{
    __shared__ unsigned int sh[NBINS];
    for (int i = threadIdx.x; i < NBINS; i += blockDim.x) sh[i] = 0u;
    __syncthreads();

    int t = slot & 1;
    float lo   = g_lo[t];
    float invw = 1.0f / g_w[t];

    int stride = gridDim.x * blockDim.x;
    for (int i = blockIdx.x * blockDim.x + threadIdx.x; i < n4; i += stride) {
        float4 v = ((const float4*)x)[i];
        float a, r;
        a = fabsf(v.x); r = (a - lo) * invw;
        if (r >= 0.0f && r < (float)NBINS) atomicAdd(&sh[(int)r], 1u);
        a = fabsf(v.y); r = (a - lo) * invw;
        if (r >= 0.0f && r < (float)NBINS) atomicAdd(&sh[(int)r], 1u);
        a = fabsf(v.z); r = (a - lo) * invw;
        if (r >= 0.0f && r < (float)NBINS) atomicAdd(&sh[(int)r], 1u);
        a = fabsf(v.w); r = (a - lo) * invw;
        if (r >= 0.0f && r < (float)NBINS) atomicAdd(&sh[(int)r], 1u);
    }
    __syncthreads();
    for (int i = threadIdx.x; i < NBINS; i += blockDim.x) {
        unsigned int c = sh[i];
        if (c) atomicAdd(&g_hist[slot][i], c);
    }
}

__global__ void pick_kernel(int t, int slot, int finalize)
{
    __shared__ unsigned int csum[256];
    __shared__ unsigned int pre[256];
    int tid = threadIdx.x;

    unsigned int local[16];
    unsigned int s = 0;
#pragma unroll
    for (int i = 0; i < 16; i++) {
        local[i] = g_hist[slot][tid * 16 + i];
        s += local[i];
    }
    csum[tid] = s;
    __syncthreads();
    if (tid == 0) {
        unsigned int acc = 0;
        for (int i = 0; i < 256; i++) { pre[i] = acc; acc += csum[i]; }
    }
    __syncthreads();

    unsigned int r = g_rank[t];
    if (pre[tid] <= r && r < pre[tid] + csum[tid]) {
        unsigned int acc = pre[tid];
#pragma unroll
        for (int i = 0; i < 16; i++) {
            if (r < acc + local[i]) {
                int b    = tid * 16 + i;
                float w  = g_w[t];
                float lo = g_lo[t] + (float)b * w;
                if (finalize) {
                    g_tau[t] = lo + 0.5f * w;
                } else {
                    g_lo[t]   = lo;
                    g_w[t]    = w / (float)NBINS;
                    g_rank[t] = r - acc;
                }
                break;
            }
            acc += local[i];
        }
    }
}

__global__ void max_kernel(const float* __restrict__ x, int n4, int t)
{
    float tau = g_tau[t];
    float m = 0.0f;
    int stride = gridDim.x * blockDim.x;
    for (int i = blockIdx.x * blockDim.x + threadIdx.x; i < n4; i += stride) {
        float4 v = ((const float4*)x)[i];
        float a;
        a = fabsf(v.x); if (a < tau) m = fmaxf(m, a);
        a = fabsf(v.y); if (a < tau) m = fmaxf(m, a);
        a = fabsf(v.z); if (a < tau) m = fmaxf(m, a);
        a = fabsf(v.w); if (a < tau) m = fmaxf(m, a);
    }
#pragma unroll
    for (int o = 16; o > 0; o >>= 1)
        m = fmaxf(m, __shfl_xor_sync(0xffffffffu, m, o));
    if ((threadIdx.x & 31) == 0)
        atomicMax(&g_maxbits[t], __float_as_uint(m));
}

__global__ void quant_kernel(const float* __restrict__ x, int n4, int t,
                             float* __restrict__ out)
{
    float tau   = g_tau[t];
    float scale = __fdiv_rn(__uint_as_float(g_maxbits[t]), 127.0f);
    int stride = gridDim.x * blockDim.x;
    for (int i = blockIdx.x * blockDim.x + threadIdx.x; i < n4; i += stride) {
        float4 v = ((const float4*)x)[i];
        float4 o;
        float a;
        a = fabsf(v.x);
        o.x = (a >= tau) ? v.x
              : fminf(fmaxf(rintf(__fdiv_rn(v.x, scale)), -128.0f), 127.0f) * scale;
        a = fabsf(v.y);
        o.y = (a >= tau) ? v.y
              : fminf(fmaxf(rintf(__fdiv_rn(v.y, scale)), -128.0f), 127.0f) * scale;
        a = fabsf(v.z);
        o.z = (a >= tau) ? v.z
              : fminf(fmaxf(rintf(__fdiv_rn(v.z, scale)), -128.0f), 127.0f) * scale;
        a = fabsf(v.w);
        o.w = (a >= tau) ? v.w
              : fminf(fmaxf(rintf(__fdiv_rn(v.w, scale)), -128.0f), 127.0f) * scale;
        ((float4*)out)[i] = o;
    }
}

// ===========================================================================
// tf32 mma.sync batched GEMM  (base-target safe: no tcgen05)
//   C[b] = A[b] (2048x2048 rm) @ B[b] (2048x2048 rm)
//   CTA 128x128, BK=32, 256 threads (8 warps 2x4), warp tile 64x32.
//   mma.sync.aligned.m16n8k8.row.col.f32.tf32.tf32.f32
//   SMEM holds fragment-permuted tiles so frag loads are LDS.128 / LDS.32.
// ===========================================================================
#define G 2048
#define BKF 32
#define NCHUNK (G / BKF)        // 64

// A buffer: 32 blocks (MT*4+kstep) x 132 floats  (lane*4 + slot, 4 pad)
#define A_BLK_STRIDE 132
#define A_BUF_FLOATS (32 * A_BLK_STRIDE)          // 4224
// B buffer: slot-major: slot*2112 + (NT*4+kstep)*33 + lane (1 pad)
#define B_SLOT_STRIDE 2112
#define B_BLK_STRIDE 33
#define B_BUF_FLOATS (2 * B_SLOT_STRIDE)          // 4224
#define DSMEM_BYTES ((2 * (A_BUF_FLOATS + B_BUF_FLOATS)) * 4)   // 67584

__device__ __forceinline__ uint32_t f2tf32(float x) {
    uint32_t y;
    asm("cvt.rna.tf32.f32 %0, %1;" : "=r"(y) : "f"(x));
    return y;
}

__device__ __forceinline__ void mma8(float* c, const uint32_t* a, const uint32_t* b)
{
    asm volatile(
        "mma.sync.aligned.m16n8k8.row.col.f32.tf32.tf32.f32 "
        "{%0,%1,%2,%3}, {%4,%5,%6,%7}, {%8,%9}, {%0,%1,%2,%3};"
        : "+f"(c[0]), "+f"(c[1]), "+f"(c[2]), "+f"(c[3])
        : "r"(a[0]), "r"(a[1]), "r"(a[2]), "r"(a[3]),
          "r"(b[0]), "r"(b[1]));
}

__global__ void __launch_bounds__(256, 2)
gemm_mma_kernel(const float* __restrict__ A, const float* __restrict__ B,
                float* __restrict__ C)
{
    extern __shared__ float sm[];
    // layout: [A0 | A1 | B0 | B1]
    const int tid = threadIdx.x;
    const int wid = tid >> 5;
    const int lid = tid & 31;
    const int warp_m = wid & 1;     // 0..1 (64 rows each)
    const int warp_n = wid >> 1;    // 0..3 (32 cols each)

    const int brow = blockIdx.y * 128;
    const int bcol = blockIdx.x * 128;
    const int z    = blockIdx.z;

    const float* Ab = A + (size_t)z * G * G + (size_t)brow * G;
    const float* Bb = B + (size_t)z * G * G + bcol;
    float*       Cb = C + (size_t)z * G * G;

    // ---- staging constants ----
    // A: flat = tid + it*256 ; row = flat>>3, c4 = flat&7 (const per thread)
    const int a_r0   = tid >> 3;        // +32 per it
    const int a_c4   = tid & 7;
    const int a_kstep = a_c4 >> 1;
    const int a_slotb = (a_c4 & 1) * 2;
    // B: flat = tid + it*256 ; k_local = flat>>5, c4 = flat&31
    const int b_k0l  = tid >> 5;        // 0..7, +8 per it (=> kstep == it)
    const int b_c4   = tid & 31;
    const int b_nt   = b_c4 >> 1;       // 0..15
    const int b_ncol = (b_c4 & 1) * 4;  // n&7 base
    const int b_kslot = (b_k0l >= 4) ? 1 : 0;
    const int b_k3   = b_k0l & 3;

    float4 av[4], bv[4];
    float acc[4][4][4];
#pragma unroll
    for (int mt = 0; mt < 4; ++mt)
#pragma unroll
        for (int nt = 0; nt < 4; ++nt)
#pragma unroll
            for (int i = 0; i < 4; ++i) acc[mt][nt][i] = 0.0f;

    // ---- prologue: load + store chunk 0 ----
    {
        const int k0 = 0;
#pragma unroll
        for (int it = 0; it < 4; ++it)
            av[it] = *(const float4*)&Ab[(size_t)(a_r0 + it * 32) * G + k0 + a_c4 * 4];
#pragma unroll
        for (int it = 0; it < 4; ++it)
            bv[it] = *(const float4*)&Bb[(size_t)(k0 + b_k0l + it * 8) * G + b_c4 * 4];
    }

    for (int chunk = 0; chunk < NCHUNK; ++chunk) {
        const int buf = chunk & 1;
        float* Ad = sm + buf * A_BUF_FLOATS;
        float* Bd = sm + 2 * A_BUF_FLOATS + buf * B_BUF_FLOATS;

        // store staged regs (chunk) into buf
        {
            uint32_t* Adu = (uint32_t*)Ad;
#pragma unroll
            for (int it = 0; it < 4; ++it) {
                int row  = a_r0 + it * 32;
                int mt   = row >> 4;
                int slot = a_slotb + ((row >> 3) & 1);
                int base = (mt * 4 + a_kstep) * A_BLK_STRIDE + (row & 7) * 16 + slot;
                float v[4] = {av[it].x, av[it].y, av[it].z, av[it].w};
#pragma unroll
                for (int i = 0; i < 4; ++i)
                    Adu[base + i * 4] = f2tf32(v[i]);
            }
            uint32_t* Bdu = (uint32_t*)Bd;
#pragma unroll
            for (int it = 0; it < 4; ++it) {
                int base = b_kslot * B_SLOT_STRIDE
                         + (b_nt * 4 + it) * B_BLK_STRIDE
                         + b_ncol * 4 + b_k3;
                float v[4] = {bv[it].x, bv[it].y, bv[it].z, bv[it].w};
#pragma unroll
                for (int i = 0; i < 4; ++i)
                    Bdu[base + i * 4] = f2tf32(v[i]);
            }
        }
        __syncthreads();

        // issue LDGs for chunk+1 early (overlap with compute)
        if (chunk + 1 < NCHUNK) {
            const int k0 = (chunk + 1) * BKF;
#pragma unroll
            for (int it = 0; it < 4; ++it)
                av[it] = *(const float4*)&Ab[(size_t)(a_r0 + it * 32) * G + k0 + a_c4 * 4];
#pragma unroll
            for (int it = 0; it < 4; ++it)
                bv[it] = *(const float4*)&Bb[(size_t)(k0 + b_k0l + it * 8) * G + b_c4 * 4];
        }

        // compute on buf
        {
            const uint32_t* Adu = (const uint32_t*)Ad;
            const uint32_t* Bdu = (const uint32_t*)Bd;
#pragma unroll
            for (int ks = 0; ks < 4; ++ks) {
                uint32_t a[4][4];
#pragma unroll
                for (int mt = 0; mt < 4; ++mt) {
                    const uint32_t* p = Adu
                        + ((warp_m * 4 + mt) * 4 + ks) * A_BLK_STRIDE + lid * 4;
                    uint4 q = *(const uint4*)p;
                    a[mt][0] = q.x; a[mt][1] = q.y; a[mt][2] = q.z; a[mt][3] = q.w;
                }
                uint32_t b[4][2];
#pragma unroll
                for (int nt = 0; nt < 4; ++nt) {
                    int off = ((warp_n * 4 + nt) * 4 + ks) * B_BLK_STRIDE + lid;
                    b[nt][0] = Bdu[off];
                    b[nt][1] = Bdu[B_SLOT_STRIDE + off];
                }
#pragma unroll
                for (int mt = 0; mt < 4; ++mt)
#pragma unroll
                    for (int nt = 0; nt < 4; ++nt)
                        mma8(acc[mt][nt], a[mt], b[nt]);
            }
        }
        __syncthreads();
    }

    // ---- epilogue ----
    const int g4 = lid >> 2;            // groupID 0..7
    const int t4 = lid & 3;             // thread-in-group
#pragma unroll
    for (int mt = 0; mt < 4; ++mt) {
        int r0 = brow + warp_m * 64 + mt * 16 + g4;
#pragma unroll
        for (int nt = 0; nt < 4; ++nt) {
            int c = bcol + warp_n * 32 + nt * 8 + t4 * 2;
            float2 v0 = make_float2(acc[mt][nt][0], acc[mt][nt][1]);
            float2 v1 = make_float2(acc[mt][nt][2], acc[mt][nt][3]);
            *(float2*)&Cb[(size_t)r0 * G + c]       = v0;
            *(float2*)&Cb[(size_t)(r0 + 8) * G + c] = v1;
        }
    }
}

// ===========================================================================
// Launch
// ===========================================================================
extern "C" void kernel_launch(void* const* d_in, const int* in_sizes, int n_in,
                              void* d_out, int out_size)
{
    const float* x1 = (const float*)d_in[0];   // [2,8,2048,2048]
    const float* x2 = (const float*)d_in[1];   // [2,8,2048,2048]
    float* out = (float*)d_out;

    const long long n  = (long long)in_sizes[0];   // 67108864
    const long long n0 = n / 2;
    const int n4  = (int)(n  / 4);
    const int n04 = (int)(n0 / 4);

    double h = 0.99 * (double)(n0 - 1);
    unsigned int rank = (unsigned int)h;

    float* res = out;
    float* x1h = out + n;
    float* x2h = out + 2 * n;

    cudaFuncSetAttribute(gemm_mma_kernel,
                         cudaFuncAttributeMaxDynamicSharedMemorySize, DSMEM_BYTES);

    zero_kernel<<<64, 256>>>(rank);

    // tf32 tensor-core batched GEMM
    dim3 grid(G / 128, G / 128, 16);
    gemm_mma_kernel<<<grid, 256, DSMEM_BYTES>>>(x1, x2, res);

    // tau for x1 (two-level histogram over |x1[0]|)
    hist_kernel<<<1184, 256>>>(x1, n04, 0);
    pick_kernel<<<1, 256>>>(0, 0, 0);
    hist_kernel<<<1184, 256>>>(x1, n04, 2);
    pick_kernel<<<1, 256>>>(0, 2, 1);

    // tau for x2 (transpose-invariant)
    hist_kernel<<<1184, 256>>>(x2, n04, 1);
    pick_kernel<<<1, 256>>>(1, 1, 0);
    hist_kernel<<<1184, 256>>>(x2, n04, 3);
    pick_kernel<<<1, 256>>>(1, 3, 1);

    // scale = max(|resid|)/127 over full tensors
    max_kernel<<<2048, 256>>>(x1, n4, 0);
    max_kernel<<<2048, 256>>>(x2, n4, 1);

    // quantize round-trips
    quant_kernel<<<2048, 256>>>(x1, n4, 0, x1h);
    quant_kernel<<<2048, 256>>>(x2, n4, 1, x2h);
}